// round 5
// baseline (speedup 1.0000x reference)
#include <cuda_runtime.h>

#define NATOMS_MAX 20000
#define NEDGES_MAX 500000
#define SLOTS 128
#define LOG2E 1.4426950408889634f
#define PI_OVER_CUT (3.14159265358979323846f / 6.0f)

// scratch
__device__ uint2  g_rec[NEDGES_MAX];              // {D, tgt|s<<20|t<<21}
__device__ float  g_g2s[NATOMS_MAX * 16];         // [n][src][8 etas]
__device__ float  g_g4s[NATOMS_MAX * 60];         // [n][ii][t*6+j*3+kk] (18 used + 2 pad per ii)
__device__ float4 g_slots[NATOMS_MAX * SLOTS];    // {mr2, cut3, cosphi, k4}
__device__ int    g_cnt[NATOMS_MAX];

__device__ __forceinline__ float ex2(float x) {
    float y; asm("ex2.approx.ftz.f32 %0, %1;" : "=f"(y) : "f"(x)); return y;
}
__device__ __forceinline__ void red4(float* p, float a, float b, float c, float d) {
    asm volatile("red.global.add.v4.f32 [%0], {%1,%2,%3,%4};"
                 :: "l"(p), "f"(a), "f"(b), "f"(c), "f"(d) : "memory");
}
__device__ __forceinline__ void red2(float* p, float a, float b) {
    asm volatile("red.global.add.v2.f32 [%0], {%1,%2};"
                 :: "l"(p), "f"(a), "f"(b) : "memory");
}
__device__ __forceinline__ float fc(float R) {
    return fmaf(0.5f, __cosf(PI_OVER_CUT * R), 0.5f);
}

// Per edge: build packed record AND accumulate G2 (fused). 1 edge/thread (fastest form).
__global__ void __launch_bounds__(256) edge_k(const int* __restrict__ an,
                                              const int* __restrict__ ei,
                                              const float* __restrict__ D,
                                              const float* __restrict__ g2_etas,
                                              int E) {
    int e = blockIdx.x * blockDim.x + threadIdx.x;
    if (e >= E) return;
    int src = __ldg(ei + e);
    int tgt = __ldg(ei + E + e);
    int s = __ldg(an + src);
    int t = __ldg(an + tgt);
    float d = __ldg(D + e);

    g_rec[e] = make_uint2(__float_as_uint(d),
                          (unsigned)tgt | ((unsigned)s << 20) | ((unsigned)t << 21));

    float cut = fc(d);
    float md2 = -d * d * LOG2E;
    const float* eta = g2_etas + (s * 2 + t) * 8;
    float v[8];
#pragma unroll
    for (int k = 0; k < 8; k++) v[k] = cut * ex2(md2 * __ldg(eta + k));

    float* o = g_g2s + tgt * 16 + s * 8;
    red4(o,     v[0], v[1], v[2], v[3]);
    red4(o + 4, v[4], v[5], v[6], v[7]);
}

// Stage 1: per triplet, compute geometry and bin a 16B record into the atom's slots
__global__ void __launch_bounds__(256) g4_scatter(const int* __restrict__ id3_ba,
                                                  const int* __restrict__ id3_ca,
                                                  const float* __restrict__ cosphi,
                                                  const float* __restrict__ g4_etas,
                                                  int T) {
    int i = blockIdx.x * blockDim.x + threadIdx.x;
    if (i >= T) return;
    int ba = __ldg(id3_ba + i);
    int ca = __ldg(id3_ca + i);
    if (ba <= ca) return;                 // triplet dedup

    float cph = __ldg(cosphi + i);
    uint2 rb = g_rec[ba];
    uint2 rc = g_rec[ca];
    float Rba = __uint_as_float(rb.x);
    float Rca = __uint_as_float(rc.x);
    if (Rba >= 6.0f || Rca >= 6.0f) return;

    float Rbc2 = fmaf(Rba, Rba, fmaf(Rca, Rca, -2.0f * Rba * Rca * cph));
    float Rbc = sqrtf(fmaxf(Rbc2, 1e-12f));
    if (Rbc >= 6.0f) return;              // in_range (zero contribution otherwise)

    int aidx = rb.y & 0xFFFFF;
    int A    = (rb.y >> 21) & 1;
    int sb   = (rb.y >> 20) & 1;
    int sc   = (rc.y >> 20) & 1;
    int t = sb + sc;
    int k4 = A * 3 + t;

    float cut3 = fc(Rba) * fc(Rca) * fc(Rbc);
    float mr2 = -(Rbc2 + Rba * Rba + Rca * Rca) * LOG2E;

    int slot = atomicAdd(&g_cnt[aidx], 1);
    if (slot < SLOTS) {
        g_slots[aidx * SLOTS + slot] =
            make_float4(mr2, cut3, cph, __int_as_float(k4));
    } else {
        // overflow fallback (statistically never): direct reduction
        float b0 = 1.0f - cph, b1 = 1.0f + cph;
        float b0s = b0 * b0, b1s = b1 * b1;
        float cl[6] = { b0, 0.5f * b0s, 0.125f * b0s * b0s,
                        b1, 0.5f * b1s, 0.125f * b1s * b1s };
#pragma unroll
        for (int ii = 0; ii < 3; ii++) {
            float rad = ex2(mr2 * __ldg(g4_etas + k4 * 3 + ii)) * cut3;
            float* o = g_g4s + aidx * 60 + ii * 20 + t * 6;
            red2(o,     rad * cl[0], rad * cl[3]);   // j order: (j,kk) -> j*3+kk
            red2(o + 2, rad * cl[1], rad * cl[4]);
            red2(o + 4, rad * cl[2], rad * cl[5]);
        }
    }
}

// Stage 2: thread (n, ii) streams atom n's slots, accumulates 18 values, 5 reds out
__global__ void __launch_bounds__(128) g4_reduce(const float* __restrict__ g4_etas, int N) {
    int idx = blockIdx.x * blockDim.x + threadIdx.x;
    if (idx >= N * 3) return;
    int n = idx / 3;
    int ii = idx - n * 3;

    int cnt = g_cnt[n];
    if (cnt > SLOTS) cnt = SLOTS;

    float acc[18];
#pragma unroll
    for (int m = 0; m < 18; m++) acc[m] = 0.0f;

    const float4* sl = g_slots + n * SLOTS;
    for (int j = 0; j < cnt; j++) {
        float4 s = sl[j];
        int k4 = __float_as_int(s.w);
        float eta = __ldg(g4_etas + k4 * 3 + ii);
        float rad = ex2(s.x * eta) * s.y;
        int t = k4 >= 3 ? k4 - 3 : k4;    // k4 % 3
        float cph = s.z;
        // zetas {1,2,4}, lambdas {-1,+1}: 2^(1-z)|1+l c|^z -> b, b^2/2, b^4/8
        float b0 = 1.0f - cph, b1 = 1.0f + cph;
        float b0s = b0 * b0, b1s = b1 * b1;
        float r0 = (t == 0) ? rad : 0.0f;
        float r1 = (t == 1) ? rad : 0.0f;
        float r2 = (t == 2) ? rad : 0.0f;
        float cl[6] = { b0, 0.5f * b0s, 0.125f * b0s * b0s,
                        b1, 0.5f * b1s, 0.125f * b1s * b1s };
        // layout within acc: t*6 + (j*3 + kk); cl order above is (kk-major per j):
        // map: [b0,b0^2/2,b0^4/8] = j=0,kk=0..2 ; [b1,...] = j=1,kk=0..2
#pragma unroll
        for (int m = 0; m < 3; m++) {
            acc[0 * 6 + m]     = fmaf(r0, cl[m],     acc[0 * 6 + m]);
            acc[0 * 6 + 3 + m] = fmaf(r0, cl[3 + m], acc[0 * 6 + 3 + m]);
            acc[1 * 6 + m]     = fmaf(r1, cl[m],     acc[1 * 6 + m]);
            acc[1 * 6 + 3 + m] = fmaf(r1, cl[3 + m], acc[1 * 6 + 3 + m]);
            acc[2 * 6 + m]     = fmaf(r2, cl[m],     acc[2 * 6 + m]);
            acc[2 * 6 + 3 + m] = fmaf(r2, cl[3 + m], acc[2 * 6 + 3 + m]);
        }
    }

    // add into g_g4s (red, so overflow-fallback contributions combine correctly)
    float* o = g_g4s + n * 60 + ii * 20;
    red4(o,      acc[0],  acc[1],  acc[2],  acc[3]);
    red4(o + 4,  acc[4],  acc[5],  acc[6],  acc[7]);
    red4(o + 8,  acc[8],  acc[9],  acc[10], acc[11]);
    red4(o + 12, acc[12], acc[13], acc[14], acc[15]);
    red2(o + 16, acc[16], acc[17]);
}

// Transpose scratch into final [N,70] layout; float2 per thread
__global__ void __launch_bounds__(256) combine_k(float2* __restrict__ out, int n2_total) {
    int i = blockIdx.x * blockDim.x + threadIdx.x;
    if (i >= n2_total) return;
    int n = i / 35;
    int c = (i - n * 35) * 2;   // even col; pair never spans g2/g4 boundary
    float2 v;
    if (c < 16) {
        const float* g2 = g_g2s + n * 16;
        v.x = g2[(c & 1) * 8 + (c >> 1)];
        v.y = g2[((c + 1) & 1) * 8 + ((c + 1) >> 1)];
    } else {
        const float* g4 = g_g4s + n * 60;
        // reference col: idx = ((ii*2+j)*3+kk)*3 + t ; our layout: ii*20 + t*6 + j*3 + kk
        int i0 = c - 16, i1 = c - 15;
        int t0 = i0 % 3, m0 = i0 / 3;
        int t1 = i1 % 3, m1 = i1 / 3;
        v.x = g4[(m0 / 6) * 20 + t0 * 6 + ((m0 / 3) & 1) * 3 + (m0 % 3)];
        v.y = g4[(m1 / 6) * 20 + t1 * 6 + ((m1 / 3) & 1) * 3 + (m1 % 3)];
    }
    out[i] = v;
}

extern "C" void kernel_launch(void* const* d_in, const int* in_sizes, int n_in,
                              void* d_out, int out_size) {
    const int*   an       = (const int*)  d_in[0];
    const int*   ei       = (const int*)  d_in[1];
    const float* D        = (const float*)d_in[2];
    const int*   id3_ba   = (const int*)  d_in[3];
    const int*   id3_ca   = (const int*)  d_in[4];
    const float* cosphi   = (const float*)d_in[5];
    const float* g2_etas  = (const float*)d_in[6];
    const float* g4_etas  = (const float*)d_in[7];

    int E = in_sizes[2];
    int T = in_sizes[3];
    int N = in_sizes[0];

    void* p_g2s; cudaGetSymbolAddress(&p_g2s, g_g2s);
    void* p_g4s; cudaGetSymbolAddress(&p_g4s, g_g4s);
    void* p_cnt; cudaGetSymbolAddress(&p_cnt, g_cnt);
    cudaMemsetAsync(p_g2s, 0, (size_t)N * 16 * sizeof(float), 0);
    cudaMemsetAsync(p_g4s, 0, (size_t)N * 60 * sizeof(float), 0);
    cudaMemsetAsync(p_cnt, 0, (size_t)N * sizeof(int), 0);

    edge_k<<<(E + 255) / 256, 256>>>(an, ei, D, g2_etas, E);
    g4_scatter<<<(T + 255) / 256, 256>>>(id3_ba, id3_ca, cosphi, g4_etas, T);
    g4_reduce<<<(N * 3 + 127) / 128, 128>>>(g4_etas, N);

    int n2 = out_size / 2;
    combine_k<<<(n2 + 255) / 256, 256>>>((float2*)d_out, n2);
}

// round 6
// speedup vs baseline: 1.3015x; 1.3015x over previous
#include <cuda_runtime.h>

#define NATOMS_MAX 20000
#define NEDGES_MAX 500000
#define LOG2E 1.4426950408889634f
#define PI_OVER_CUT (3.14159265358979323846f / 6.0f)

// scratch (accumulators + packed edge records)
__device__ uint2 g_rec[NEDGES_MAX];        // {D, tgt|s<<20|t<<21}
__device__ float g_g2s[NATOMS_MAX * 16];   // [n][src_species][8 etas]
__device__ float g_g4s[NATOMS_MAX * 60];   // [n][trip][18 vals + 2 pad], 16B blocks

__device__ __forceinline__ float ex2(float x) {
    float y; asm("ex2.approx.ftz.f32 %0, %1;" : "=f"(y) : "f"(x)); return y;
}
__device__ __forceinline__ void red4(float* p, float a, float b, float c, float d) {
    asm volatile("red.global.add.v4.f32 [%0], {%1,%2,%3,%4};"
                 :: "l"(p), "f"(a), "f"(b), "f"(c), "f"(d) : "memory");
}
__device__ __forceinline__ void red2(float* p, float a, float b) {
    asm volatile("red.global.add.v2.f32 [%0], {%1,%2};"
                 :: "l"(p), "f"(a), "f"(b) : "memory");
}
__device__ __forceinline__ float fc(float R) {
    return fmaf(0.5f, __cosf(PI_OVER_CUT * R), 0.5f);
}

// Per edge: build packed record AND accumulate G2 (fused). 1 edge/thread (R2 form).
__global__ void __launch_bounds__(256) edge_k(const int* __restrict__ an,
                                              const int* __restrict__ ei,
                                              const float* __restrict__ D,
                                              const float* __restrict__ g2_etas,
                                              int E) {
    int e = blockIdx.x * blockDim.x + threadIdx.x;
    if (e >= E) return;
    int src = __ldg(ei + e);
    int tgt = __ldg(ei + E + e);
    int s = __ldg(an + src);
    int t = __ldg(an + tgt);
    float d = __ldg(D + e);

    g_rec[e] = make_uint2(__float_as_uint(d),
                          (unsigned)tgt | ((unsigned)s << 20) | ((unsigned)t << 21));

    float cut = fc(d);
    float md2 = -d * d * LOG2E;
    const float* eta = g2_etas + (s * 2 + t) * 8;
    float v[8];
#pragma unroll
    for (int k = 0; k < 8; k++) v[k] = cut * ex2(md2 * __ldg(eta + k));

    float* o = g_g2s + tgt * 16 + s * 8;
    red4(o,     v[0], v[1], v[2], v[3]);
    red4(o + 4, v[4], v[5], v[6], v[7]);
}

__global__ void __launch_bounds__(256) g4_k(const int* __restrict__ id3_ba,
                                            const int* __restrict__ id3_ca,
                                            const float* __restrict__ cosphi,
                                            const float* __restrict__ g4_etas,
                                            int T) {
    int i = blockIdx.x * blockDim.x + threadIdx.x;
    if (i >= T) return;
    int ba = __ldg(id3_ba + i);
    int ca = __ldg(id3_ca + i);
    if (ba <= ca) return;                 // triplet dedup

    float cph = __ldg(cosphi + i);
    uint2 rb = g_rec[ba];
    uint2 rc = g_rec[ca];
    float Rba = __uint_as_float(rb.x);
    float Rca = __uint_as_float(rc.x);
    if (Rba >= 6.0f || Rca >= 6.0f) return;

    float Rbc2 = fmaf(Rba, Rba, fmaf(Rca, Rca, -2.0f * Rba * Rca * cph));
    float Rbc = sqrtf(fmaxf(Rbc2, 1e-12f));
    if (Rbc >= 6.0f) return;

    int aidx = rb.y & 0xFFFFF;
    int A    = (rb.y >> 21) & 1;          // central atom species (an_tgt of ba)
    int sb   = (rb.y >> 20) & 1;
    int sc   = (rc.y >> 20) & 1;
    int t = sb + sc;                      // (0,0)->0 (0,1)/(1,0)->1 (1,1)->2
    int k4 = A * 3 + t;

    float cut3 = fc(Rba) * fc(Rca) * fc(Rbc);
    float r2 = Rbc2 + Rba * Rba + Rca * Rca;

    const float* eta = g4_etas + k4 * 3;
    float mr2 = -r2 * LOG2E;
    float rad[3];
#pragma unroll
    for (int ii = 0; ii < 3; ii++) rad[ii] = ex2(mr2 * __ldg(eta + ii)) * cut3;

    // zetas = {1,2,4}, lambdas = {-1,+1} (fixed by setup_inputs), cosphi in [-1,1]:
    // 2^(1-z)*|1+l*c|^z  ->  b, b^2/2, b^4/8 with b = 1 + l*c >= 0
    float b0 = 1.0f - cph;
    float b1 = 1.0f + cph;
    float b0s = b0 * b0, b1s = b1 * b1;
    float cl[2][3] = {
        { b0, 0.5f * b0s, 0.125f * b0s * b0s },
        { b1, 0.5f * b1s, 0.125f * b1s * b1s } };

    float v[18];
#pragma unroll
    for (int ii = 0; ii < 3; ii++)
#pragma unroll
        for (int j = 0; j < 2; j++)
#pragma unroll
            for (int kk = 0; kk < 3; kk++)
                v[(ii * 2 + j) * 3 + kk] = rad[ii] * cl[j][kk];

    float* o = g_g4s + aidx * 60 + t * 20;   // 16B-aligned block of 18 (+2 pad)
    red4(o,      v[0],  v[1],  v[2],  v[3]);
    red4(o + 4,  v[4],  v[5],  v[6],  v[7]);
    red4(o + 8,  v[8],  v[9],  v[10], v[11]);
    red4(o + 12, v[12], v[13], v[14], v[15]);
    red2(o + 16, v[16], v[17]);
}

// Transpose scratch into final [N,70] layout; 2x float2 per thread (ILP)
__global__ void __launch_bounds__(256) combine_k(float2* __restrict__ out,
                                                 int n2_total, int n2_half) {
    int i0 = blockIdx.x * blockDim.x + threadIdx.x;
#pragma unroll
    for (int r = 0; r < 2; r++) {
        int i = i0 + r * n2_half;
        if (i >= n2_total) return;
        int n = i / 35;
        int c = (i - n * 35) * 2;   // even col; pair never spans g2/g4 boundary
        float2 v;
        if (c < 16) {
            const float* g2 = g_g2s + n * 16;
            v.x = g2[(c & 1) * 8 + (c >> 1)];
            v.y = g2[((c + 1) & 1) * 8 + ((c + 1) >> 1)];
        } else {
            const float* g4 = g_g4s + n * 60;
            int i0c = c - 16, i1c = c - 15;
            v.x = g4[(i0c % 3) * 20 + i0c / 3];
            v.y = g4[(i1c % 3) * 20 + i1c / 3];
        }
        out[i] = v;
    }
}

extern "C" void kernel_launch(void* const* d_in, const int* in_sizes, int n_in,
                              void* d_out, int out_size) {
    const int*   an       = (const int*)  d_in[0];
    const int*   ei       = (const int*)  d_in[1];
    const float* D        = (const float*)d_in[2];
    const int*   id3_ba   = (const int*)  d_in[3];
    const int*   id3_ca   = (const int*)  d_in[4];
    const float* cosphi   = (const float*)d_in[5];
    const float* g2_etas  = (const float*)d_in[6];
    const float* g4_etas  = (const float*)d_in[7];

    int E = in_sizes[2];
    int T = in_sizes[3];
    int N = in_sizes[0];

    void* p_g2s; cudaGetSymbolAddress(&p_g2s, g_g2s);
    void* p_g4s; cudaGetSymbolAddress(&p_g4s, g_g4s);
    cudaMemsetAsync(p_g2s, 0, (size_t)N * 16 * sizeof(float), 0);
    cudaMemsetAsync(p_g4s, 0, (size_t)N * 60 * sizeof(float), 0);

    edge_k<<<(E + 255) / 256, 256>>>(an, ei, D, g2_etas, E);
    g4_k<<<(T + 255) / 256, 256>>>(id3_ba, id3_ca, cosphi, g4_etas, T);

    int n2 = out_size / 2;
    int n2_half = (n2 + 1) / 2;
    combine_k<<<(n2_half + 255) / 256, 256>>>((float2*)d_out, n2, n2_half);
}